// round 15
// baseline (speedup 1.0000x reference)
#include <cuda_runtime.h>
#include <cuda_fp16.h>
#include <math.h>
#include <cstdint>

#define BSZ  16      // batch
#define NCAP 1152    // primary caps
#define DP   8       // dim primary
#define DDIG 10      // digit caps
#define DD   16      // dim digit
#define JP   (DD/2)  // half2 pairs per row = 8

#define TILE_N 16
#define NT (NCAP / TILE_N)   // 72

#define K2CH 9               // k2 chunks per b
#define K2N (NCAP / K2CH)    // 128

// Scratch (device globals; fully overwritten every call)
__device__ __align__(16) __half2 g_Uh[BSZ * DDIG * NCAP * JP];  // U_hat fp16 (5.9 MB)
__device__ __align__(16) float g_Tp[BSZ * DDIG * DD * NT];      // T tile partials (fp32)
__device__ __align__(16) float g_wgt[BSZ * DDIG * NCAP];        // weights [b][d][n]

// -------------------------------------------------------------------------
// K1: votes — R3-proven shape (256 thr, thread=(nl,j), 16-b loop) with
// half2 stores via one shfl-pair per b. T tile-partials, no atomics.
// Grid (DDIG, NT) = 720 CTAs x 256 threads.
// -------------------------------------------------------------------------
__global__ __launch_bounds__(256) void k1_votes(
    const float* __restrict__ u,   // [B][N][DP]
    const float* __restrict__ W)   // [D][N][DD][DP]
{
    const int d    = blockIdx.x;
    const int tile = blockIdx.y;
    const int n0   = tile * TILE_N;
    const int t    = threadIdx.x;
    const int j    = t & 15;
    const int nl   = t >> 4;
    const int n    = n0 + nl;
    const int lane = t & 31;
    const int w    = t >> 5;

    // Issue W DRAM loads FIRST (overlap latency with staging + sync)
    const float4* wp = reinterpret_cast<const float4*>(
        W + ((size_t)(d * NCAP + n) * DD + j) * DP);
    const float4 w0 = wp[0];
    const float4 w1 = wp[1];

    __shared__ __align__(16) float us[BSZ][TILE_N][DP];   // 8 KB
    __shared__ float red[BSZ][8][DD];                     // 8 KB

    // Stage u tile: 512 float4; 2 per thread
    #pragma unroll
    for (int it = 0; it < 2; ++it) {
        const int idx = it * 256 + t;
        const int b   = idx >> 5;
        const int rem = idx & 31;
        const float4 v = reinterpret_cast<const float4*>(
            u + (size_t)b * NCAP * DP + (size_t)n0 * DP)[rem];
        reinterpret_cast<float4*>(&us[b][0][0])[rem] = v;
    }
    __syncthreads();

    __half2* Urow = g_Uh + ((size_t)d * NCAP + n) * JP + (j >> 1);

    #pragma unroll
    for (int b = 0; b < BSZ; ++b) {
        const float4* up = reinterpret_cast<const float4*>(&us[b][nl][0]);
        const float4 u0 = up[0];
        const float4 u1 = up[1];
        const float acc = w0.x * u0.x + w0.y * u0.y + w0.z * u0.z + w0.w * u0.w
                        + w1.x * u1.x + w1.y * u1.y + w1.z * u1.z + w1.w * u1.w;

        // pair j with j^1 for half2; even-j lanes store (predicated, no branch)
        const float accN = __shfl_xor_sync(0xffffffffu, acc, 1);
        if (!(j & 1))
            Urow[(size_t)b * (DDIG * NCAP * JP)] = __floats2half2_rn(acc, accN);

        // T partial over nl: warp holds nl = {2w, 2w+1}; xor16 pairs them
        const float ps = acc + __shfl_xor_sync(0xffffffffu, acc, 16);
        if (lane < 16) red[b][w][lane] = ps;   // lane == j for nl even
    }
    __syncthreads();

    // 256 threads -> (b, j): sum 8 warp partials, store tile partial
    {
        const int b2 = t >> 4;
        const int j2 = t & 15;
        float s = 0.f;
        #pragma unroll
        for (int ww = 0; ww < 8; ++ww) s += red[b2][ww][j2];
        g_Tp[((size_t)(b2 * DDIG + d) * DD + j2) * NT + tile] = s;
    }
}

// -------------------------------------------------------------------------
// K2: streaming softmax weights. Grid (BSZ, 9) x 128 threads; thread = one n.
// High MLP: 20 independent LDG.128 over the 10 d rows (half2 data).
// -------------------------------------------------------------------------
__global__ __launch_bounds__(128) void k2_wgt(
    const float* __restrict__ Bp)   // [D][1][N]
{
    const int b  = blockIdx.x;
    const int ch = blockIdx.y;
    const int t  = threadIdx.x;

    __shared__ float Tsm[DDIG][DD];

    // T[b,d,j] from 72 contiguous tile partials (18 f4 per (d,j))
    for (int idx = t; idx < DDIG * DD; idx += 128) {
        const float4* p = reinterpret_cast<const float4*>(
            &g_Tp[(size_t)(b * DDIG * DD + idx) * NT]);
        float s = 0.f;
        #pragma unroll
        for (int k = 0; k < NT / 4; ++k) {
            const float4 v = p[k];
            s += v.x + v.y + v.z + v.w;
        }
        Tsm[idx >> 4][idx & 15] = s;
    }
    __syncthreads();

    const int n = ch * K2N + t;
    const float inv_sqrt8 = 0.3535533905932738f;

    float a[DDIG];
    #pragma unroll
    for (int d = 0; d < DDIG; ++d) {
        const uint4* r = reinterpret_cast<const uint4*>(
            g_Uh + ((size_t)(b * DDIG + d) * NCAP + n) * JP);
        const uint4 A = r[0];
        const uint4 B = r[1];
        const float* T = Tsm[d];
        float s = 0.f;
        {
            const float2 f0 = __half22float2(*reinterpret_cast<const __half2*>(&A.x));
            const float2 f1 = __half22float2(*reinterpret_cast<const __half2*>(&A.y));
            const float2 f2 = __half22float2(*reinterpret_cast<const __half2*>(&A.z));
            const float2 f3 = __half22float2(*reinterpret_cast<const __half2*>(&A.w));
            s += T[0] * f0.x + T[1] * f0.y + T[2] * f1.x + T[3] * f1.y
               + T[4] * f2.x + T[5] * f2.y + T[6] * f3.x + T[7] * f3.y;
        }
        {
            const float2 f0 = __half22float2(*reinterpret_cast<const __half2*>(&B.x));
            const float2 f1 = __half22float2(*reinterpret_cast<const __half2*>(&B.y));
            const float2 f2 = __half22float2(*reinterpret_cast<const __half2*>(&B.z));
            const float2 f3 = __half22float2(*reinterpret_cast<const __half2*>(&B.w));
            s += T[8]  * f0.x + T[9]  * f0.y + T[10] * f1.x + T[11] * f1.y
               + T[12] * f2.x + T[13] * f2.y + T[14] * f3.x + T[15] * f3.y;
        }
        a[d] = s * inv_sqrt8;
    }

    float m = a[0];
    #pragma unroll
    for (int d = 1; d < DDIG; ++d) m = fmaxf(m, a[d]);
    float e[DDIG], denom = 0.f;
    #pragma unroll
    for (int d = 0; d < DDIG; ++d) { e[d] = __expf(a[d] - m); denom += e[d]; }
    const float rden = 1.f / denom;

    #pragma unroll
    for (int d = 0; d < DDIG; ++d)
        g_wgt[((size_t)(b * DDIG + d)) * NCAP + n] =
            e[d] * rden + __ldg(&Bp[(size_t)d * NCAP + n]);
}

// -------------------------------------------------------------------------
// K3: S[b,d,:] = sum_n wgt[b,d,n] * U[b,d,n,:]; inline squash.
// Grid (160) x 512 threads; thread=(jp 0..7, ng 0..63). Coalesced half2.
// No atomics, no fences — each CTA owns its (b,d) end-to-end.
// -------------------------------------------------------------------------
__global__ __launch_bounds__(512) void k3_out(float* __restrict__ out)
{
    const int bd   = blockIdx.x;      // b*DDIG + d
    const int t    = threadIdx.x;
    const int jp   = t & 7;
    const int ng   = t >> 3;          // 0..63
    const int lane = t & 31;
    const int w    = t >> 5;          // 0..15

    __shared__ float wgs[NCAP];       // 4.6 KB
    __shared__ float2 red[16][JP];    // 1 KB
    __shared__ float Ssm[DD];
    __shared__ float coef_sh;

    const float* wg = g_wgt + (size_t)bd * NCAP;
    for (int idx = t; idx < NCAP / 4; idx += 512)
        reinterpret_cast<float4*>(wgs)[idx] =
            reinterpret_cast<const float4*>(wg)[idx];
    __syncthreads();

    const __half2* Ub = g_Uh + (size_t)bd * NCAP * JP;

    float2 acc = make_float2(0.f, 0.f);
    #pragma unroll
    for (int k = 0; k < NCAP / 64; ++k) {     // 18 iters, independent loads
        const int n = k * 64 + ng;
        const float2 f = __half22float2(Ub[(size_t)n * JP + jp]);
        const float wv = wgs[n];
        acc.x += wv * f.x;
        acc.y += wv * f.y;
    }

    // reduce over ng-within-warp (lane>>3): xor8 + xor16
    acc.x += __shfl_xor_sync(0xffffffffu, acc.x, 8);
    acc.x += __shfl_xor_sync(0xffffffffu, acc.x, 16);
    acc.y += __shfl_xor_sync(0xffffffffu, acc.y, 8);
    acc.y += __shfl_xor_sync(0xffffffffu, acc.y, 16);
    if (lane < 8) red[w][lane] = acc;
    __syncthreads();

    if (t < JP) {
        float sx = 0.f, sy = 0.f;
        #pragma unroll
        for (int ww = 0; ww < 16; ++ww) {
            const float2 v = red[ww][t];
            sx += v.x; sy += v.y;
        }
        Ssm[2 * t]     = sx;
        Ssm[2 * t + 1] = sy;
    }
    __syncthreads();
    if (t == 0) {
        float nn = 0.f;
        #pragma unroll
        for (int jj = 0; jj < DD; ++jj) nn += Ssm[jj] * Ssm[jj];
        const float norm = sqrtf(nn);
        const float EPS  = 1e-7f;
        coef_sh = (1.f - 1.f / (__expf(norm) + EPS)) / (norm + EPS);
    }
    __syncthreads();
    if (t < DD)
        out[(size_t)bd * DD + t] = coef_sh * Ssm[t];
}

// -------------------------------------------------------------------------
extern "C" void kernel_launch(void* const* d_in, const int* in_sizes, int n_in,
                              void* d_out, int out_size)
{
    const float* u  = (const float*)d_in[0];   // primary_caps [16,1152,8]
    const float* W  = (const float*)d_in[1];   // W            [10,1152,16,8]
    const float* Bp = (const float*)d_in[2];   // B_prior      [10,1,1152]
    float* out      = (float*)d_out;           // [16,10,16]

    (void)in_sizes; (void)n_in; (void)out_size;

    k1_votes<<<dim3(DDIG, NT), 256>>>(u, W);
    k2_wgt  <<<dim3(BSZ, K2CH), 128>>>(Bp);
    k3_out  <<<BSZ * DDIG, 512>>>(out);
}

// round 16
// speedup vs baseline: 1.0889x; 1.0889x over previous
#include <cuda_runtime.h>
#include <math.h>
#include <cstdint>

#define BSZ  16
#define NCAP 1152
#define DP   8
#define DDIG 10
#define DD   16

#define TILE_N 16
#define NT   (NCAP / TILE_N)    // 72
#define NUA  (DDIG * NT)        // 720 phase-A units

#define BCH  18                 // phase-B chunks per b
#define BN   (NCAP / BCH)       // 64
#define NUB  (BSZ * BCH)        // 288 phase-B units
#define NUC  (BSZ * DDIG)       // 160 phase-C units

#define GRID 296                // 2 CTAs/SM: all resident (CTAS_ACTIVE{2:148})

// Scratch (device globals; zero-init at load; g_T re-zeroed every call)
__device__ __align__(16) float g_U  [BSZ * DDIG * NCAP * DD];   // 11.8 MB
__device__ __align__(16) float g_T  [BSZ * DDIG * DD];
__device__ __align__(16) float g_wgt[BSZ * DDIG * NCAP];
__device__ unsigned long long g_bar[2];                         // monotonic tickets

// ---- software grid barrier: monotonic ticket, graph-replay safe ----
__device__ __forceinline__ void grid_barrier(int id)
{
    __syncthreads();
    __threadfence();
    if (threadIdx.x == 0) {
        const unsigned long long old = atomicAdd(&g_bar[id], 1ULL);
        const unsigned long long tgt = (old / GRID + 1ULL) * (unsigned long long)GRID;
        unsigned long long v;
        do {
            asm volatile("ld.global.cg.u64 %0, [%1];" : "=l"(v) : "l"(g_bar + id));
            if (v < tgt) __nanosleep(128);
        } while (v < tgt);
    }
    __syncthreads();
}

// -------------------------------------------------------------------------
// Persistent fused kernel: votes+T | barrier | softmax wgt | barrier |
// combine+squash. One launch, no gaps.
// -------------------------------------------------------------------------
__global__ __launch_bounds__(256, 2) void fused_caps(
    const float* __restrict__ u,   // [B][N][DP]
    const float* __restrict__ W,   // [D][N][DD][DP]
    const float* __restrict__ Bp,  // [D][1][N]
    float* __restrict__ out)       // [B][D][DD]
{
    __shared__ __align__(16) char smraw[17408];
    const int t = threadIdx.x;

    // ================= Phase A: votes + atomic T (proven R7 shape) =========
    {
        float (*us)[TILE_N][DP] = reinterpret_cast<float(*)[TILE_N][DP]>(smraw);          // 8 KB
        float (*red)[8][DD]     = reinterpret_cast<float(*)[8][DD]>(smraw + 8192);        // 8 KB

        const int j    = t & 15;
        const int nl   = t >> 4;
        const int lane = t & 31;
        const int w    = t >> 5;

        for (int unit = blockIdx.x; unit < NUA; unit += GRID) {
            const int d  = unit % DDIG;
            const int n0 = (unit / DDIG) * TILE_N;
            const int n  = n0 + nl;

            __syncthreads();   // smem reuse guard across units

            const float4* wp = reinterpret_cast<const float4*>(
                W + ((size_t)(d * NCAP + n) * DD + j) * DP);
            const float4 w0 = wp[0];
            const float4 w1 = wp[1];

            #pragma unroll
            for (int it = 0; it < 2; ++it) {
                const int idx = it * 256 + t;
                const int b   = idx >> 5;
                const int rm  = idx & 31;
                reinterpret_cast<float4*>(&us[b][0][0])[rm] =
                    reinterpret_cast<const float4*>(
                        u + (size_t)b * NCAP * DP + (size_t)n0 * DP)[rm];
            }
            __syncthreads();

            #pragma unroll
            for (int b = 0; b < BSZ; ++b) {
                const float4* up = reinterpret_cast<const float4*>(&us[b][nl][0]);
                const float4 u0 = up[0];
                const float4 u1 = up[1];
                const float acc = w0.x * u0.x + w0.y * u0.y + w0.z * u0.z + w0.w * u0.w
                                + w1.x * u1.x + w1.y * u1.y + w1.z * u1.z + w1.w * u1.w;
                g_U[((size_t)(b * DDIG + d) * NCAP + n) * DD + j] = acc;

                const float ps = acc + __shfl_xor_sync(0xffffffffu, acc, 16);
                if (lane < 16) red[b][w][lane] = ps;
            }
            __syncthreads();

            {
                const int b2 = t >> 4;
                const int j2 = t & 15;
                float s = 0.f;
                #pragma unroll
                for (int ww = 0; ww < 8; ++ww) s += red[b2][ww][j2];
                atomicAdd(&g_T[(b2 * DDIG + d) * DD + j2], s);
            }
        }
    }

    grid_barrier(0);

    // ================= Phase B: softmax weights ============================
    {
        float* Ts        = reinterpret_cast<float*>(smraw);           // 160 f
        float (*a_s)[12] = reinterpret_cast<float(*)[12]>(smraw + 1024); // 64x12

        const float inv_sqrt8 = 0.3535533905932738f;

        for (int unit = blockIdx.x; unit < NUB; unit += GRID) {
            const int b  = unit / BCH;
            const int ch = unit % BCH;

            __syncthreads();
            if (t < DDIG * DD) Ts[t] = __ldcg(&g_T[b * DDIG * DD + t]);
            __syncthreads();

            const int dq = t >> 6;        // 0..3
            const int nl = t & 63;
            const int n  = ch * BN + nl;

            #pragma unroll
            for (int d = dq; d < DDIG; d += 4) {
                const float4* r = reinterpret_cast<const float4*>(
                    g_U + ((size_t)(b * DDIG + d) * NCAP + n) * DD);
                const float4 v0 = r[0], v1 = r[1], v2 = r[2], v3 = r[3];
                const float* T = Ts + d * DD;
                a_s[nl][d] =
                    (T[0]  * v0.x + T[1]  * v0.y + T[2]  * v0.z + T[3]  * v0.w
                   + T[4]  * v1.x + T[5]  * v1.y + T[6]  * v1.z + T[7]  * v1.w
                   + T[8]  * v2.x + T[9]  * v2.y + T[10] * v2.z + T[11] * v2.w
                   + T[12] * v3.x + T[13] * v3.y + T[14] * v3.z + T[15] * v3.w)
                   * inv_sqrt8;
            }
            __syncthreads();

            if (t < BN) {
                const int n2 = ch * BN + t;
                float a[DDIG];
                #pragma unroll
                for (int d = 0; d < DDIG; ++d) a[d] = a_s[t][d];
                float m = a[0];
                #pragma unroll
                for (int d = 1; d < DDIG; ++d) m = fmaxf(m, a[d]);
                float denom = 0.f;
                #pragma unroll
                for (int d = 0; d < DDIG; ++d) { a[d] = __expf(a[d] - m); denom += a[d]; }
                const float rden = 1.f / denom;
                #pragma unroll
                for (int d = 0; d < DDIG; ++d)
                    g_wgt[((size_t)(b * DDIG + d)) * NCAP + n2] =
                        a[d] * rden + __ldg(&Bp[(size_t)d * NCAP + n2]);
            }
        }
    }

    grid_barrier(1);

    // reset T for next call (all phase-B reads done; phase C never touches T)
    for (int idx = blockIdx.x * 256 + t; idx < BSZ * DDIG * DD; idx += GRID * 256)
        g_T[idx] = 0.f;

    // ================= Phase C: combine + squash ===========================
    {
        float*  wgs  = reinterpret_cast<float*>(smraw);                // 1152 f (4608 B)
        float4 (*redc)[4] = reinterpret_cast<float4(*)[4]>(smraw + 4864); // [8][4] f4
        float*  Ssm  = reinterpret_cast<float*>(smraw + 5376);         // 16 f
        float*  coef = reinterpret_cast<float*>(smraw + 5440);         // 1 f

        const int jq   = t & 3;
        const int ng   = t >> 2;          // 0..63
        const int lane = t & 31;
        const int w5   = t >> 5;

        for (int unit = blockIdx.x; unit < NUC; unit += GRID) {
            const int bd = unit;          // b*DDIG + d

            __syncthreads();
            for (int idx = t; idx < NCAP / 4; idx += 256)
                reinterpret_cast<float4*>(wgs)[idx] =
                    __ldcg(reinterpret_cast<const float4*>(g_wgt + (size_t)bd * NCAP) + idx);
            __syncthreads();

            float4 acc = make_float4(0.f, 0.f, 0.f, 0.f);
            #pragma unroll
            for (int k = 0; k < NCAP / 64; ++k) {      // 18 iters
                const int n = k * 64 + ng;
                const float4 v = *reinterpret_cast<const float4*>(
                    g_U + ((size_t)bd * NCAP + n) * DD + jq * 4);
                const float wv = wgs[n];
                acc.x += wv * v.x;
                acc.y += wv * v.y;
                acc.z += wv * v.z;
                acc.w += wv * v.w;
            }

            // reduce over ng within warp (warp = 8 ng x 4 jq): strides 4,8,16
            #pragma unroll
            for (int off = 4; off <= 16; off <<= 1) {
                acc.x += __shfl_xor_sync(0xffffffffu, acc.x, off);
                acc.y += __shfl_xor_sync(0xffffffffu, acc.y, off);
                acc.z += __shfl_xor_sync(0xffffffffu, acc.z, off);
                acc.w += __shfl_xor_sync(0xffffffffu, acc.w, off);
            }
            if (lane < 4) redc[w5][lane] = acc;        // lane == jq
            __syncthreads();

            if (t < 4) {
                float4 s = make_float4(0.f, 0.f, 0.f, 0.f);
                #pragma unroll
                for (int ww = 0; ww < 8; ++ww) {
                    const float4 v = redc[ww][t];
                    s.x += v.x; s.y += v.y; s.z += v.z; s.w += v.w;
                }
                Ssm[t * 4 + 0] = s.x;
                Ssm[t * 4 + 1] = s.y;
                Ssm[t * 4 + 2] = s.z;
                Ssm[t * 4 + 3] = s.w;
            }
            __syncthreads();
            if (t == 0) {
                float nn = 0.f;
                #pragma unroll
                for (int jj = 0; jj < DD; ++jj) nn += Ssm[jj] * Ssm[jj];
                const float norm = sqrtf(nn);
                const float EPS  = 1e-7f;
                coef[0] = (1.f - 1.f / (__expf(norm) + EPS)) / (norm + EPS);
            }
            __syncthreads();
            if (t < DD)
                out[(size_t)bd * DD + t] = coef[0] * Ssm[t];
        }
    }
}

// -------------------------------------------------------------------------
extern "C" void kernel_launch(void* const* d_in, const int* in_sizes, int n_in,
                              void* d_out, int out_size)
{
    const float* u  = (const float*)d_in[0];   // primary_caps [16,1152,8]
    const float* W  = (const float*)d_in[1];   // W            [10,1152,16,8]
    const float* Bp = (const float*)d_in[2];   // B_prior      [10,1,1152]
    float* out      = (float*)d_out;           // [16,10,16]

    (void)in_sizes; (void)n_in; (void)out_size;

    fused_caps<<<GRID, 256>>>(u, W, Bp, out);
}